// round 12
// baseline (speedup 1.0000x reference)
#include <cuda_runtime.h>
#include <cuda_bf16.h>
#include <cstdint>

#define NN 20000
#define EE 320000
#define H 128
#define FIN 14
#define FOUT 9
#define NLAYERS 6
#define NM 132
#define ASTR 136          // bf16 operand row stride (elems) -> 272 B

#define MD_PROJ 0
#define MD_BOTH 1
#define MD_AGG  2

// ---------------- device scratch ----------------
__device__ float g_h[NN * H];
__device__ float g_Pbuf[2][NN * 256];     // double-buffered projections
__device__ float g_invdeg[NN];
__device__ int   g_src[EE];
__device__ int   g_dst[EE];
__device__ int   g_cnt[NN];
__device__ int   g_off[NN + 1];
__device__ int   g_ssrc[EE];
__device__ float4 g_sea[EE];
__device__ int   g_is64;
// prebuilt B-operand images (transposed, padded, hi/lo)
__device__ __align__(16) __nv_bfloat16 g_W2h[NLAYERS * H * ASTR];
__device__ __align__(16) __nv_bfloat16 g_W2l[NLAYERS * H * ASTR];
__device__ __align__(16) __nv_bfloat16 g_W1h[NLAYERS * 256 * ASTR];
__device__ __align__(16) __nv_bfloat16 g_W1l[NLAYERS * 256 * ASTR];

__device__ __forceinline__ float silu_m(float x) {
    return __fdividef(x, 1.0f + __expf(-x));
}

__device__ __forceinline__ uint32_t smem_u32(const void* p) {
    uint32_t a;
    asm("{ .reg .u64 t; cvta.to.shared.u64 t, %1; cvt.u32.u64 %0, t; }" : "=r"(a) : "l"(p));
    return a;
}

__device__ __forceinline__ void ldsm4(uint32_t* r, uint32_t addr) {
    asm volatile("ldmatrix.sync.aligned.m8n8.x4.shared.b16 {%0,%1,%2,%3}, [%4];"
                 : "=r"(r[0]), "=r"(r[1]), "=r"(r[2]), "=r"(r[3]) : "r"(addr));
}

__device__ __forceinline__ void mma16816(float* d, const uint32_t* a,
                                         uint32_t b0, uint32_t b1) {
    asm volatile(
        "mma.sync.aligned.m16n8k16.row.col.f32.bf16.bf16.f32 "
        "{%0,%1,%2,%3}, {%4,%5,%6,%7}, {%8,%9}, {%0,%1,%2,%3};"
        : "+f"(d[0]), "+f"(d[1]), "+f"(d[2]), "+f"(d[3])
        : "r"(a[0]), "r"(a[1]), "r"(a[2]), "r"(a[3]), "r"(b0), "r"(b1));
}

__device__ __forceinline__ uint32_t pack_bf16x2(float a, float b) {
    __nv_bfloat162 t;
    t.x = __float2bfloat16_rn(a);
    t.y = __float2bfloat16_rn(b);
    return *(uint32_t*)&t;
}

// ---------------- preprocessing ----------------
__global__ void k_pre0(const int* __restrict__ ei) {
    int i = blockIdx.x * blockDim.x + threadIdx.x;
    if (i < NN) g_cnt[i] = 0;
    if (blockIdx.x == 0) {
        __shared__ int cnt;
        if (threadIdx.x == 0) cnt = 0;
        __syncthreads();
        int c = 0;
        for (int k = threadIdx.x; k < 1024; k += 256)
            if (ei[2 * k + 1] != 0) c++;
        if (c) atomicAdd(&cnt, c);
        __syncthreads();
        if (threadIdx.x == 0) g_is64 = (cnt == 0) ? 1 : 0;
    }
}

__global__ void k_convert(const void* __restrict__ ei) {
    int i = blockIdx.x * blockDim.x + threadIdx.x;
    if (i >= EE) return;
    int s, d;
    if (g_is64) {
        const long long* p = (const long long*)ei;
        s = (int)p[i];
        d = (int)p[EE + i];
    } else {
        const int* p = (const int*)ei;
        s = p[i];
        d = p[EE + i];
    }
    g_src[i] = s;
    g_dst[i] = d;
    atomicAdd(&g_cnt[d], 1);
}

// scan g_cnt -> g_off (exclusive), compute invdeg, reset cnt
__global__ void k_scan() {
    __shared__ int wsum[32];
    __shared__ int carry;
    const int lane = threadIdx.x & 31;
    const int wp = threadIdx.x >> 5;
    if (threadIdx.x == 0) carry = 0;
    __syncthreads();
    for (int base = 0; base < NN; base += 1024) {
        int i = base + threadIdx.x;
        int v = (i < NN) ? g_cnt[i] : 0;
        int s = v;
#pragma unroll
        for (int dlt = 1; dlt < 32; dlt <<= 1) {
            int t = __shfl_up_sync(0xFFFFFFFFu, s, dlt);
            if (lane >= dlt) s += t;
        }
        __syncthreads();
        if (lane == 31) wsum[wp] = s;
        __syncthreads();
        if (wp == 0) {
            int ws = wsum[lane];
#pragma unroll
            for (int dlt = 1; dlt < 32; dlt <<= 1) {
                int t = __shfl_up_sync(0xFFFFFFFFu, ws, dlt);
                if (lane >= dlt) ws += t;
            }
            wsum[lane] = ws;
        }
        __syncthreads();
        int excl = carry + s - v + (wp > 0 ? wsum[wp - 1] : 0);
        if (i < NN) {
            g_off[i] = excl;
            g_invdeg[i] = 1.0f / fmaxf((float)v, 1.0f);
            g_cnt[i] = 0;
        }
        __syncthreads();
        if (threadIdx.x == 0) carry += wsum[31];
    }
    if (threadIdx.x == 0) g_off[NN] = EE;
}

__global__ void k_scatter(const float* __restrict__ ea) {
    int e = blockIdx.x * blockDim.x + threadIdx.x;
    if (e >= EE) return;
    int d = g_dst[e];
    int pos = g_off[d] + atomicAdd(&g_cnt[d], 1);
    g_ssrc[pos] = g_src[e];
    float4 v;
    v.x = ea[e * 3 + 0];
    v.y = ea[e * 3 + 1];
    v.z = ea[e * 3 + 2];
    v.w = 0.0f;
    g_sea[pos] = v;
    // after this: g_cnt[d] == deg(d) (mask source for k_layer epilogue)
}

// ---------------- weight image prep (merged) ----------------
#define W2_TOT (NLAYERS * H * H)          // 98304
#define W1_TOT (NLAYERS * 256 * H)        // 196608
__global__ void k_prepw(const float* __restrict__ W2, const float* __restrict__ W1) {
    int i = blockIdx.x * 256 + threadIdx.x;
    if (i < W2_TOT) {
        int l = i >> 14, r = i & 16383, n = r >> 7, k = r & 127;
        float w = W2[(size_t)l * 16384 + k * H + n];
        __nv_bfloat16 hi = __float2bfloat16_rn(w);
        __nv_bfloat16 lo = __float2bfloat16_rn(w - __bfloat162float(hi));
        size_t off = (size_t)l * H * ASTR + n * ASTR + k;
        g_W2h[off] = hi;
        g_W2l[off] = lo;
    } else if (i < W2_TOT + W1_TOT) {
        int j = i - W2_TOT;
        int l = j >> 15, r = j & 32767, n = r >> 7, k = r & 127;
        int row = ((n >> 7) << 7) + k;
        float w = W1[(size_t)l * 259 * H + row * H + (n & 127)];
        __nv_bfloat16 hi = __float2bfloat16_rn(w);
        __nv_bfloat16 lo = __float2bfloat16_rn(w - __bfloat162float(hi));
        size_t off = (size_t)l * 256 * ASTR + n * ASTR + k;
        g_W1h[off] = hi;
        g_W1l[off] = lo;
    }
}

// ---------------- tiled encoder ----------------
#define EN_XS 0
#define EN_W1 (EN_XS + FIN * NM * 4)
#define EN_TS (EN_W1 + FIN * H * 4)
#define EN_BS (EN_TS + H * NM * 4)
#define EN_B1 (EN_BS + 32 * NM * 4)
#define EN_B2 (EN_B1 + 512)
#define EN_SMEM (EN_B2 + 512)

__global__ void __launch_bounds__(256, 2)
k_encoder2(const float* __restrict__ x,
           const float* __restrict__ w1, const float* __restrict__ b1,
           const float* __restrict__ w2, const float* __restrict__ b2) {
    extern __shared__ char smb[];
    float* Xs  = (float*)(smb + EN_XS);
    float* W1s = (float*)(smb + EN_W1);
    float* Ts  = (float*)(smb + EN_TS);
    float* Bs  = (float*)(smb + EN_BS);
    float* sB1 = (float*)(smb + EN_B1);
    float* sB2 = (float*)(smb + EN_B2);
    const int n0 = blockIdx.x * 128;
    const int tid = threadIdx.x;
    const int tx = tid & 15, ty = tid >> 4;
    const int row0 = ty * 8, col0 = tx * 8;

    for (int i = tid; i < FIN * 128; i += 256) {
        int k = i >> 7, nd = i & 127;
        Xs[k * NM + nd] = (n0 + nd < NN) ? x[(size_t)(n0 + nd) * FIN + k] : 0.0f;
        W1s[i] = w1[i];
    }
    if (tid < 128) { sB1[tid] = b1[tid]; sB2[tid] = b2[tid]; }
    __syncthreads();

    {
        float acc[8][8];
#pragma unroll
        for (int r = 0; r < 8; r++)
#pragma unroll
            for (int c = 0; c < 8; c++) acc[r][c] = 0.0f;
#pragma unroll
        for (int k = 0; k < FIN; k++) {
            float av[8], bv[8];
#pragma unroll
            for (int r = 0; r < 8; r++) av[r] = Xs[k * NM + row0 + r];
#pragma unroll
            for (int c = 0; c < 8; c++) bv[c] = W1s[k * 128 + col0 + c];
#pragma unroll
            for (int r = 0; r < 8; r++)
#pragma unroll
                for (int c = 0; c < 8; c++) acc[r][c] += av[r] * bv[c];
        }
#pragma unroll
        for (int r = 0; r < 8; r++)
#pragma unroll
            for (int c = 0; c < 8; c++)
                Ts[(col0 + c) * NM + row0 + r] = silu_m(acc[r][c] + sB1[col0 + c]);
    }
    __syncthreads();

    {
        float acc[8][8];
#pragma unroll
        for (int r = 0; r < 8; r++)
#pragma unroll
            for (int c = 0; c < 8; c++) acc[r][c] = 0.0f;
        for (int t = 0; t < 4; t++) {
#pragma unroll
            for (int it = 0; it < 4; ++it) {
                int i = tid + it * 256;
                int rowk = i >> 5, c4 = i & 31;
                *(float4*)&Bs[rowk * NM + c4 * 4] =
                    *(const float4*)&w2[(size_t)(t * 32 + rowk) * H + c4 * 4];
            }
            __syncthreads();
#pragma unroll 4
            for (int kk = 0; kk < 32; ++kk) {
                float av[8], bv[8];
                int k = t * 32 + kk;
#pragma unroll
                for (int r = 0; r < 8; r++) av[r] = Ts[k * NM + row0 + r];
                float4 b0 = *(const float4*)&Bs[kk * NM + col0];
                float4 b1v = *(const float4*)&Bs[kk * NM + col0 + 4];
                bv[0] = b0.x; bv[1] = b0.y; bv[2] = b0.z; bv[3] = b0.w;
                bv[4] = b1v.x; bv[5] = b1v.y; bv[6] = b1v.z; bv[7] = b1v.w;
#pragma unroll
                for (int r = 0; r < 8; r++)
#pragma unroll
                    for (int c = 0; c < 8; c++) acc[r][c] += av[r] * bv[c];
            }
            __syncthreads();
        }
#pragma unroll
        for (int r = 0; r < 8; r++) {
            int node = n0 + row0 + r;
            if (node < NN) {
                float* hp = &g_h[(size_t)node * H + col0];
                *(float4*)hp = make_float4(acc[r][0] + sB2[col0 + 0], acc[r][1] + sB2[col0 + 1],
                                           acc[r][2] + sB2[col0 + 2], acc[r][3] + sB2[col0 + 3]);
                *(float4*)(hp + 4) = make_float4(acc[r][4] + sB2[col0 + 4], acc[r][5] + sB2[col0 + 5],
                                                 acc[r][6] + sB2[col0 + 6], acc[r][7] + sB2[col0 + 7]);
            }
        }
    }
}

// ---------------- fused layer: edge sum -> HMMA agg -> residual -> proj --
#define NB_AH 0
#define NB_AL 17408
#define NB_BH 34816
#define NB_BL 69632
#define NB_B2 104448
#define NB_MK 104960
#define NB_SMEM 105216

// warp-tile mma: 32 rows x 32 cols, 3-term bf16
__device__ __forceinline__ void mma_tile(uint32_t aH, uint32_t aL,
                                         uint32_t bH, uint32_t bL,
                                         int mrow, int ncol, int lid,
                                         float d[2][4][4]) {
    const int a_r = lid & 15, a_c8 = (lid >> 4) * 8;
    const int b_g = lid >> 3;
    const int b_n = (b_g >> 1) * 8 + (lid & 7);
    const int b_c8 = (b_g & 1) * 8;
#pragma unroll 1
    for (int ks = 0; ks < 8; ks++) {
        const int k0 = ks * 16;
        uint32_t ah[2][4], al[2][4];
#pragma unroll
        for (int mt = 0; mt < 2; mt++) {
            uint32_t addr = aH + (uint32_t)(mrow + mt * 16 + a_r) * 272
                          + (uint32_t)(k0 + a_c8) * 2;
            ldsm4(ah[mt], addr);
            ldsm4(al[mt], addr + (aL - aH));
        }
#pragma unroll
        for (int bt = 0; bt < 2; bt++) {
            uint32_t bh[4], bl[4];
            uint32_t addr = bH + (uint32_t)(ncol + bt * 16 + b_n) * 272
                          + (uint32_t)(k0 + b_c8) * 2;
            ldsm4(bh, addr);
            ldsm4(bl, addr + (bL - bH));
            const int nt0 = bt * 2, nt1 = nt0 + 1;
#pragma unroll
            for (int mt = 0; mt < 2; mt++) {
                mma16816(d[mt][nt0], ah[mt], bh[0], bh[1]);
                mma16816(d[mt][nt1], ah[mt], bh[2], bh[3]);
                mma16816(d[mt][nt0], ah[mt], bl[0], bl[1]);
                mma16816(d[mt][nt1], ah[mt], bl[2], bl[3]);
                mma16816(d[mt][nt0], al[mt], bh[0], bh[1]);
                mma16816(d[mt][nt1], al[mt], bh[2], bh[3]);
            }
        }
    }
}

__global__ void __launch_bounds__(256, 2)
k_layer(int layer, const float* __restrict__ W1, const float* __restrict__ b1,
        const float* __restrict__ b2, int mode, int pin) {
    extern __shared__ char smb[];
    const uint32_t sb = smem_u32(smb);
    float* sB2 = (float*)(smb + NB_B2);
    float* sMk = (float*)(smb + NB_MK);
    const int tid = threadIdx.x;
    const int lid = tid & 31;
    const int wid = tid >> 5;
    const int n0 = blockIdx.x * 64;
    const int mrow = (wid & 1) * 32;
    const int ncol = (wid >> 1) * 32;
    const int fr = lid >> 2, fc = (lid & 3) * 2;
    const float* Pin = g_Pbuf[pin];            // edge-phase reads
    float* Pout = g_Pbuf[pin ^ 1];             // phase-B writes (other buffer!)

    if (mode != MD_PROJ) {
        if (tid < 128) sB2[tid] = b2[tid];
        if (tid < 64) {
            int node = n0 + tid;
            sMk[tid] = (node < NN && g_cnt[node] > 0) ? 1.0f : 0.0f;
        }
        // W2 image copy issued first so its LDGs overlap the edge loop
        {
            const uint4* srcH = (const uint4*)(g_W2h + (size_t)layer * H * ASTR);
            const uint4* srcL = (const uint4*)(g_W2l + (size_t)layer * H * ASTR);
            uint4* dstH = (uint4*)(smb + NB_BH);
            uint4* dstL = (uint4*)(smb + NB_BL);
            for (int i = tid; i < 2176; i += 256) { dstH[i] = srcH[i]; dstL[i] = srcL[i]; }
        }

        // ---- fused edge phase: zsum for 8 nodes/warp, straight into As ----
        {
            const int c = lid * 4;
            const float4 wa = *(const float4*)&W1[256 * H + c];
            const float4 wb = *(const float4*)&W1[257 * H + c];
            const float4 wc = *(const float4*)&W1[258 * H + c];
            const float4 bbv = *(const float4*)&b1[c];
#pragma unroll 1
            for (int q = 0; q < 8; q++) {
                const int r = wid * 8 + q;
                const int node = n0 + r;
                float4 acc = make_float4(0.f, 0.f, 0.f, 0.f);
                if (node < NN) {
                    const float4 pa = *(const float4*)&Pin[(size_t)node * 256 + c];
                    const float bx = pa.x + bbv.x, by = pa.y + bbv.y;
                    const float bz = pa.z + bbv.z, bw = pa.w + bbv.w;
                    int e = g_off[node];
                    const int end = g_off[node + 1];
                    if (e < end) {
                        int src = g_ssrc[e];
                        float4 eav = g_sea[e];
                        float4 pb = *(const float4*)&Pin[(size_t)src * 256 + 128 + c];
                        while (e < end) {
                            const int en = e + 1;
                            int srcN = src; float4 eavN = eav; float4 pbN = pb;
                            if (en < end) {
                                srcN = g_ssrc[en];
                                eavN = g_sea[en];
                                pbN = *(const float4*)&Pin[(size_t)srcN * 256 + 128 + c];
                            }
                            float v0 = bx + pb.x + eav.x * wa.x + eav.y * wb.x + eav.z * wc.x;
                            float v1 = by + pb.y + eav.x * wa.y + eav.y * wb.y + eav.z * wc.y;
                            float v2 = bz + pb.z + eav.x * wa.z + eav.y * wb.z + eav.z * wc.z;
                            float v3 = bw + pb.w + eav.x * wa.w + eav.y * wb.w + eav.z * wc.w;
                            acc.x += silu_m(v0);
                            acc.y += silu_m(v1);
                            acc.z += silu_m(v2);
                            acc.w += silu_m(v3);
                            e = en; src = srcN; eav = eavN; pb = pbN;
                        }
                    }
                    const float iv = g_invdeg[node];
                    acc.x *= iv; acc.y *= iv; acc.z *= iv; acc.w *= iv;
                }
                __nv_bfloat16 h0 = __float2bfloat16_rn(acc.x), h1 = __float2bfloat16_rn(acc.y);
                __nv_bfloat16 h2 = __float2bfloat16_rn(acc.z), h3 = __float2bfloat16_rn(acc.w);
                uint2 uh, ul;
                uh.x = pack_bf16x2(acc.x, acc.y);
                uh.y = pack_bf16x2(acc.z, acc.w);
                ul.x = pack_bf16x2(acc.x - __bfloat162float(h0), acc.y - __bfloat162float(h1));
                ul.y = pack_bf16x2(acc.z - __bfloat162float(h2), acc.w - __bfloat162float(h3));
                *(uint2*)(smb + NB_AH + r * 272 + lid * 8) = uh;
                *(uint2*)(smb + NB_AL + r * 272 + lid * 8) = ul;
            }
        }
        __syncthreads();

        float d[2][4][4];
#pragma unroll
        for (int mt = 0; mt < 2; mt++)
#pragma unroll
            for (int nt = 0; nt < 4; nt++)
#pragma unroll
                for (int q = 0; q < 4; q++) d[mt][nt][q] = 0.0f;
        mma_tile(sb + NB_AH, sb + NB_AL, sb + NB_BH, sb + NB_BL, mrow, ncol, lid, d);
        __syncthreads();

        // epilogue: h_new = h + D + b2*mask -> g_h (+ As hi/lo if BOTH)
#pragma unroll
        for (int mt = 0; mt < 2; mt++) {
#pragma unroll
            for (int nt = 0; nt < 4; nt++) {
                int c = ncol + nt * 8 + fc;
#pragma unroll
                for (int half8 = 0; half8 < 2; half8++) {
                    int r = mrow + mt * 16 + fr + half8 * 8;
                    int node = n0 + r;
                    float d0 = d[mt][nt][half8 * 2 + 0];
                    float d1 = d[mt][nt][half8 * 2 + 1];
                    float hn0 = 0.f, hn1 = 0.f;
                    if (node < NN) {
                        float mk = sMk[r];
                        float2 hv = *(const float2*)&g_h[(size_t)node * H + c];
                        hn0 = hv.x + d0 + sB2[c] * mk;
                        hn1 = hv.y + d1 + sB2[c + 1] * mk;
                        *(float2*)&g_h[(size_t)node * H + c] = make_float2(hn0, hn1);
                    }
                    if (mode == MD_BOTH) {
                        __nv_bfloat16 b0 = __float2bfloat16_rn(hn0);
                        __nv_bfloat16 b1v = __float2bfloat16_rn(hn1);
                        *(uint32_t*)(smb + NB_AH + r * 272 + c * 2) = pack_bf16x2(hn0, hn1);
                        *(uint32_t*)(smb + NB_AL + r * 272 + c * 2) =
                            pack_bf16x2(hn0 - __bfloat162float(b0), hn1 - __bfloat162float(b1v));
                    }
                }
            }
        }
        if (mode == MD_AGG) return;
    } else {
        // PROJ: convert g_h tile -> As hi/lo
#pragma unroll
        for (int it = 0; it < 8; ++it) {
            int i = tid + it * 256;
            int nd = i >> 5, seg = i & 31;
            int node = n0 + nd;
            float4 v = make_float4(0.f, 0.f, 0.f, 0.f);
            if (node < NN) v = *(const float4*)&g_h[(size_t)node * H + seg * 4];
            __nv_bfloat16 h0 = __float2bfloat16_rn(v.x), h1 = __float2bfloat16_rn(v.y);
            __nv_bfloat16 h2 = __float2bfloat16_rn(v.z), h3 = __float2bfloat16_rn(v.w);
            uint2 uh, ul;
            uh.x = pack_bf16x2(v.x, v.y);
            uh.y = pack_bf16x2(v.z, v.w);
            ul.x = pack_bf16x2(v.x - __bfloat162float(h0), v.y - __bfloat162float(h1));
            ul.y = pack_bf16x2(v.z - __bfloat162float(h2), v.w - __bfloat162float(h3));
            *(uint2*)(smb + NB_AH + nd * 272 + seg * 8) = uh;
            *(uint2*)(smb + NB_AL + nd * 272 + seg * 8) = ul;
        }
    }

    // phase B: P_next = h_new @ [W1a | W1b] of layer lw -> OTHER buffer
    const int lw = (mode == MD_PROJ) ? 0 : layer + 1;
    for (int half = 0; half < 2; half++) {
        {
            const uint4* srcH = (const uint4*)(g_W1h + (size_t)(lw * 256 + half * 128) * ASTR);
            const uint4* srcL = (const uint4*)(g_W1l + (size_t)(lw * 256 + half * 128) * ASTR);
            uint4* dstH = (uint4*)(smb + NB_BH);
            uint4* dstL = (uint4*)(smb + NB_BL);
            for (int i = tid; i < 2176; i += 256) { dstH[i] = srcH[i]; dstL[i] = srcL[i]; }
        }
        __syncthreads();

        float d[2][4][4];
#pragma unroll
        for (int mt = 0; mt < 2; mt++)
#pragma unroll
            for (int nt = 0; nt < 4; nt++)
#pragma unroll
                for (int q = 0; q < 4; q++) d[mt][nt][q] = 0.0f;
        mma_tile(sb + NB_AH, sb + NB_AL, sb + NB_BH, sb + NB_BL, mrow, ncol, lid, d);

#pragma unroll
        for (int mt = 0; mt < 2; mt++) {
#pragma unroll
            for (int nt = 0; nt < 4; nt++) {
                int c = ncol + nt * 8 + fc;
#pragma unroll
                for (int half8 = 0; half8 < 2; half8++) {
                    int r = mrow + mt * 16 + fr + half8 * 8;
                    int node = n0 + r;
                    if (node < NN) {
                        *(float2*)&Pout[(size_t)node * 256 + half * 128 + c] =
                            make_float2(d[mt][nt][half8 * 2 + 0], d[mt][nt][half8 * 2 + 1]);
                    }
                }
            }
        }
        __syncthreads();
    }
}

// ---------------- tiled decoder ----------------
#define DE_HS 0
#define DE_BS (DE_HS + 128 * NM * 4)
#define DE_W3 (DE_BS + 32 * NM * 4)
#define DE_B1 (DE_W3 + 64 * FOUT * 4)
#define DE_B2 (DE_B1 + 512)
#define DE_B3 (DE_B2 + 256)
#define DE_SMEM (DE_B3 + 64)

__global__ void __launch_bounds__(256, 2)
k_decoder2(const float* __restrict__ w1, const float* __restrict__ b1,
           const float* __restrict__ w2, const float* __restrict__ b2,
           const float* __restrict__ w3, const float* __restrict__ b3,
           float* __restrict__ out) {
    extern __shared__ char smb[];
    float* Hs  = (float*)(smb + DE_HS);
    float* Bs  = (float*)(smb + DE_BS);
    float* w3s = (float*)(smb + DE_W3);
    float* sb1 = (float*)(smb + DE_B1);
    float* sb2 = (float*)(smb + DE_B2);
    float* sb3 = (float*)(smb + DE_B3);
    const int n0 = blockIdx.x * 128;
    const int tid = threadIdx.x;
    const int tx = tid & 15, ty = tid >> 4;
    const int row0 = ty * 8, col0 = tx * 8;

#pragma unroll
    for (int it = 0; it < 16; ++it) {
        int i = tid + it * 256;
        int nd = i >> 5, seg = i & 31;
        int node = n0 + nd;
        float4 v = make_float4(0.f, 0.f, 0.f, 0.f);
        if (node < NN) v = *(const float4*)&g_h[(size_t)node * H + seg * 4];
        Hs[(seg * 4 + 0) * NM + nd] = v.x;
        Hs[(seg * 4 + 1) * NM + nd] = v.y;
        Hs[(seg * 4 + 2) * NM + nd] = v.z;
        Hs[(seg * 4 + 3) * NM + nd] = v.w;
    }
    for (int i = tid; i < 64 * FOUT; i += 256) w3s[i] = w3[i];
    if (tid < 128) sb1[tid] = b1[tid];
    if (tid < 64) sb2[tid] = b2[tid];
    if (tid < FOUT) sb3[tid] = b3[tid];
    __syncthreads();

    float acc[8][8];
#pragma unroll
    for (int r = 0; r < 8; r++)
#pragma unroll
        for (int c = 0; c < 8; c++) acc[r][c] = 0.0f;
    for (int t = 0; t < 4; t++) {
#pragma unroll
        for (int it = 0; it < 4; ++it) {
            int i = tid + it * 256;
            int rowk = i >> 5, c4 = i & 31;
            *(float4*)&Bs[rowk * NM + c4 * 4] =
                *(const float4*)&w1[(size_t)(t * 32 + rowk) * H + c4 * 4];
        }
        __syncthreads();
#pragma unroll 4
        for (int kk = 0; kk < 32; ++kk) {
            int k = t * 32 + kk;
            float av[8], bv[8];
#pragma unroll
            for (int r = 0; r < 8; r++) av[r] = Hs[k * NM + row0 + r];
            float4 b0 = *(const float4*)&Bs[kk * NM + col0];
            float4 b1v = *(const float4*)&Bs[kk * NM + col0 + 4];
            bv[0] = b0.x; bv[1] = b0.y; bv[2] = b0.z; bv[3] = b0.w;
            bv[4] = b1v.x; bv[5] = b1v.y; bv[6] = b1v.z; bv[7] = b1v.w;
#pragma unroll
            for (int r = 0; r < 8; r++)
#pragma unroll
                for (int c = 0; c < 8; c++) acc[r][c] += av[r] * bv[c];
        }
        __syncthreads();
    }
#pragma unroll
    for (int r = 0; r < 8; r++)
#pragma unroll
        for (int c = 0; c < 8; c++)
            Hs[(col0 + c) * NM + row0 + r] = silu_m(acc[r][c] + sb1[col0 + c]);
    __syncthreads();

    const int col0b = tx * 4;
    float acc2[8][4];
#pragma unroll
    for (int r = 0; r < 8; r++)
#pragma unroll
        for (int c = 0; c < 4; c++) acc2[r][c] = 0.0f;
    for (int t = 0; t < 4; t++) {
#pragma unroll
        for (int it = 0; it < 2; ++it) {
            int i = tid + it * 256;
            int rowk = i >> 4, c4 = i & 15;
            *(float4*)&Bs[rowk * NM + c4 * 4] =
                *(const float4*)&w2[(size_t)(t * 32 + rowk) * 64 + c4 * 4];
        }
        __syncthreads();
#pragma unroll 4
        for (int kk = 0; kk < 32; ++kk) {
            int k = t * 32 + kk;
            float av[8];
#pragma unroll
            for (int r = 0; r < 8; r++) av[r] = Hs[k * NM + row0 + r];
            float4 b0 = *(const float4*)&Bs[kk * NM + col0b];
            float bv[4] = {b0.x, b0.y, b0.z, b0.w};
#pragma unroll
            for (int r = 0; r < 8; r++)
#pragma unroll
                for (int c = 0; c < 4; c++) acc2[r][c] += av[r] * bv[c];
        }
        __syncthreads();
    }
#pragma unroll
    for (int r = 0; r < 8; r++)
#pragma unroll
        for (int c = 0; c < 4; c++)
            Hs[(col0b + c) * NM + row0 + r] = silu_m(acc2[r][c] + sb2[col0b + c]);
    __syncthreads();

    {
        const int nd = tid >> 1;
        const int half = tid & 1;
        const int cbase = half * 5;
        const int ncols = half ? 4 : 5;
        float a3[5];
#pragma unroll
        for (int j = 0; j < 5; j++) a3[j] = 0.0f;
        for (int k = 0; k < 64; k++) {
            float tv = Hs[k * NM + nd];
#pragma unroll
            for (int j = 0; j < 5; j++)
                if (j < ncols) a3[j] += tv * w3s[k * FOUT + cbase + j];
        }
        int node = n0 + nd;
        if (node < NN) {
            for (int j = 0; j < ncols; j++)
                out[(size_t)node * FOUT + cbase + j] = a3[j] + sb3[cbase + j];
        }
    }
}

// ---------------- launch ----------------
extern "C" void kernel_launch(void* const* d_in, const int* in_sizes, int n_in,
                              void* d_out, int out_size) {
    const float* x      = (const float*)d_in[0];
    const void*  ei     = d_in[1];
    const float* ea     = (const float*)d_in[2];
    const float* enc_w1 = (const float*)d_in[3];
    const float* enc_b1 = (const float*)d_in[4];
    const float* enc_w2 = (const float*)d_in[5];
    const float* enc_b2 = (const float*)d_in[6];
    const float* conv_w1 = (const float*)d_in[7];
    const float* conv_b1 = (const float*)d_in[8];
    const float* conv_w2 = (const float*)d_in[9];
    const float* conv_b2 = (const float*)d_in[10];
    const float* dec_w1 = (const float*)d_in[11];
    const float* dec_b1 = (const float*)d_in[12];
    const float* dec_w2 = (const float*)d_in[13];
    const float* dec_b2 = (const float*)d_in[14];
    const float* dec_w3 = (const float*)d_in[15];
    const float* dec_b3 = (const float*)d_in[16];

    cudaFuncSetAttribute(k_encoder2, cudaFuncAttributeMaxDynamicSharedMemorySize, EN_SMEM);
    cudaFuncSetAttribute(k_layer, cudaFuncAttributeMaxDynamicSharedMemorySize, NB_SMEM);
    cudaFuncSetAttribute(k_decoder2, cudaFuncAttributeMaxDynamicSharedMemorySize, DE_SMEM);

    k_pre0<<<(NN + 255) / 256, 256>>>((const int*)ei);
    k_convert<<<(EE + 255) / 256, 256>>>(ei);
    k_scan<<<1, 1024>>>();
    k_scatter<<<(EE + 255) / 256, 256>>>(ea);
    k_prepw<<<(W2_TOT + W1_TOT + 255) / 256, 256>>>(conv_w2, conv_w1);

    const int nTiles = (NN + 127) / 128;   // 157
    const int nT64   = (NN + 63) / 64;     // 313
    k_encoder2<<<nTiles, 256, EN_SMEM>>>(x, enc_w1, enc_b1, enc_w2, enc_b2);
    // PROJ writes Pbuf[pin^1]; with pin=1 it writes buffer 0
    k_layer<<<nT64, 256, NB_SMEM>>>(0, conv_w1, conv_b1, conv_b2, MD_PROJ, 1);

    for (int l = 0; l < NLAYERS; l++) {
        // layer l reads buffer (l&1)==... : layer0 reads 0, writes 1; layer1 reads 1, writes 0; ...
        k_layer<<<nT64, 256, NB_SMEM>>>(l,
                                        conv_w1 + (size_t)l * 259 * H,
                                        conv_b1 + (size_t)l * H,
                                        conv_b2 + (size_t)l * H,
                                        (l + 1 < NLAYERS) ? MD_BOTH : MD_AGG,
                                        l & 1);
    }

    k_decoder2<<<nTiles, 256, DE_SMEM>>>(dec_w1, dec_b1, dec_w2, dec_b2,
                                         dec_w3, dec_b3, (float*)d_out);
}

// round 13
// speedup vs baseline: 1.3939x; 1.3939x over previous
#include <cuda_runtime.h>
#include <cuda_bf16.h>
#include <cstdint>

#define NN 20000
#define EE 320000
#define H 128
#define FIN 14
#define FOUT 9
#define NLAYERS 6
#define NM 132
#define ASTR 136          // bf16 operand row stride (elems) -> 272 B

#define MD_PROJ 0
#define MD_BOTH 1
#define MD_AGG  2

// ---------------- device scratch ----------------
__device__ float g_h[NN * H];
__device__ float g_zsum[NN * H];
__device__ float g_P[NN * 256];
__device__ float g_invdeg[NN];
__device__ int   g_src[EE];
__device__ int   g_dst[EE];
__device__ int   g_cnt[NN];
__device__ int   g_off[NN + 1];
__device__ int   g_ssrc[EE];
__device__ float4 g_sea[EE];
__device__ int   g_is64;
// prebuilt B-operand images (transposed, padded, hi/lo)
__device__ __align__(16) __nv_bfloat16 g_W2h[NLAYERS * H * ASTR];
__device__ __align__(16) __nv_bfloat16 g_W2l[NLAYERS * H * ASTR];
__device__ __align__(16) __nv_bfloat16 g_W1h[NLAYERS * 256 * ASTR];
__device__ __align__(16) __nv_bfloat16 g_W1l[NLAYERS * 256 * ASTR];

__device__ __forceinline__ float silu_m(float x) {
    return __fdividef(x, 1.0f + __expf(-x));
}

__device__ __forceinline__ uint32_t smem_u32(const void* p) {
    uint32_t a;
    asm("{ .reg .u64 t; cvta.to.shared.u64 t, %1; cvt.u32.u64 %0, t; }" : "=r"(a) : "l"(p));
    return a;
}

__device__ __forceinline__ void ldsm4(uint32_t* r, uint32_t addr) {
    asm volatile("ldmatrix.sync.aligned.m8n8.x4.shared.b16 {%0,%1,%2,%3}, [%4];"
                 : "=r"(r[0]), "=r"(r[1]), "=r"(r[2]), "=r"(r[3]) : "r"(addr));
}

__device__ __forceinline__ void mma16816(float* d, const uint32_t* a,
                                         uint32_t b0, uint32_t b1) {
    asm volatile(
        "mma.sync.aligned.m16n8k16.row.col.f32.bf16.bf16.f32 "
        "{%0,%1,%2,%3}, {%4,%5,%6,%7}, {%8,%9}, {%0,%1,%2,%3};"
        : "+f"(d[0]), "+f"(d[1]), "+f"(d[2]), "+f"(d[3])
        : "r"(a[0]), "r"(a[1]), "r"(a[2]), "r"(a[3]), "r"(b0), "r"(b1));
}

__device__ __forceinline__ uint32_t pack_bf16x2(float a, float b) {
    __nv_bfloat162 t;
    t.x = __float2bfloat16_rn(a);
    t.y = __float2bfloat16_rn(b);
    return *(uint32_t*)&t;
}

// ---------------- preprocessing (launch-dieted) ----------------
__global__ void k_pre0(const int* __restrict__ ei) {
    int i = blockIdx.x * blockDim.x + threadIdx.x;
    if (i < NN) g_cnt[i] = 0;
    if (blockIdx.x == 0) {
        __shared__ int cnt;
        if (threadIdx.x == 0) cnt = 0;
        __syncthreads();
        int c = 0;
        for (int k = threadIdx.x; k < 1024; k += 256)
            if (ei[2 * k + 1] != 0) c++;
        if (c) atomicAdd(&cnt, c);
        __syncthreads();
        if (threadIdx.x == 0) g_is64 = (cnt == 0) ? 1 : 0;
    }
}

__global__ void k_convert(const void* __restrict__ ei) {
    int i = blockIdx.x * blockDim.x + threadIdx.x;
    if (i >= EE) return;
    int s, d;
    if (g_is64) {
        const long long* p = (const long long*)ei;
        s = (int)p[i];
        d = (int)p[EE + i];
    } else {
        const int* p = (const int*)ei;
        s = p[i];
        d = p[EE + i];
    }
    g_src[i] = s;
    g_dst[i] = d;
    atomicAdd(&g_cnt[d], 1);
}

// scan g_cnt -> g_off (exclusive), compute invdeg, reset cnt
__global__ void k_scan() {
    __shared__ int wsum[32];
    __shared__ int carry;
    const int lane = threadIdx.x & 31;
    const int wp = threadIdx.x >> 5;
    if (threadIdx.x == 0) carry = 0;
    __syncthreads();
    for (int base = 0; base < NN; base += 1024) {
        int i = base + threadIdx.x;
        int v = (i < NN) ? g_cnt[i] : 0;
        int s = v;
#pragma unroll
        for (int dlt = 1; dlt < 32; dlt <<= 1) {
            int t = __shfl_up_sync(0xFFFFFFFFu, s, dlt);
            if (lane >= dlt) s += t;
        }
        __syncthreads();
        if (lane == 31) wsum[wp] = s;
        __syncthreads();
        if (wp == 0) {
            int ws = wsum[lane];
#pragma unroll
            for (int dlt = 1; dlt < 32; dlt <<= 1) {
                int t = __shfl_up_sync(0xFFFFFFFFu, ws, dlt);
                if (lane >= dlt) ws += t;
            }
            wsum[lane] = ws;
        }
        __syncthreads();
        int excl = carry + s - v + (wp > 0 ? wsum[wp - 1] : 0);
        if (i < NN) {
            g_off[i] = excl;
            g_invdeg[i] = 1.0f / fmaxf((float)v, 1.0f);
            g_cnt[i] = 0;
        }
        __syncthreads();
        if (threadIdx.x == 0) carry += wsum[31];
    }
    if (threadIdx.x == 0) g_off[NN] = EE;
}

__global__ void k_scatter(const float* __restrict__ ea) {
    int e = blockIdx.x * blockDim.x + threadIdx.x;
    if (e >= EE) return;
    int d = g_dst[e];
    int pos = g_off[d] + atomicAdd(&g_cnt[d], 1);
    g_ssrc[pos] = g_src[e];
    float4 v;
    v.x = ea[e * 3 + 0];
    v.y = ea[e * 3 + 1];
    v.z = ea[e * 3 + 2];
    v.w = 0.0f;
    g_sea[pos] = v;
    // after this: g_cnt[d] == deg(d) (mask source for k_nodemlp)
}

// ---------------- weight image prep (merged) ----------------
#define W2_TOT (NLAYERS * H * H)          // 98304
#define W1_TOT (NLAYERS * 256 * H)        // 196608
__global__ void k_prepw(const float* __restrict__ W2, const float* __restrict__ W1) {
    int i = blockIdx.x * 256 + threadIdx.x;
    if (i < W2_TOT) {
        int l = i >> 14, r = i & 16383, n = r >> 7, k = r & 127;
        float w = W2[(size_t)l * 16384 + k * H + n];
        __nv_bfloat16 hi = __float2bfloat16_rn(w);
        __nv_bfloat16 lo = __float2bfloat16_rn(w - __bfloat162float(hi));
        size_t off = (size_t)l * H * ASTR + n * ASTR + k;
        g_W2h[off] = hi;
        g_W2l[off] = lo;
    } else if (i < W2_TOT + W1_TOT) {
        int j = i - W2_TOT;
        int l = j >> 15, r = j & 32767, n = r >> 7, k = r & 127;
        int row = ((n >> 7) << 7) + k;
        float w = W1[(size_t)l * 259 * H + row * H + (n & 127)];
        __nv_bfloat16 hi = __float2bfloat16_rn(w);
        __nv_bfloat16 lo = __float2bfloat16_rn(w - __bfloat162float(hi));
        size_t off = (size_t)l * 256 * ASTR + n * ASTR + k;
        g_W1h[off] = hi;
        g_W1l[off] = lo;
    }
}

// ---------------- tiled encoder ----------------
#define EN_XS 0
#define EN_W1 (EN_XS + FIN * NM * 4)
#define EN_TS (EN_W1 + FIN * H * 4)
#define EN_BS (EN_TS + H * NM * 4)
#define EN_B1 (EN_BS + 32 * NM * 4)
#define EN_B2 (EN_B1 + 512)
#define EN_SMEM (EN_B2 + 512)

__global__ void __launch_bounds__(256, 2)
k_encoder2(const float* __restrict__ x,
           const float* __restrict__ w1, const float* __restrict__ b1,
           const float* __restrict__ w2, const float* __restrict__ b2) {
    extern __shared__ char smb[];
    float* Xs  = (float*)(smb + EN_XS);
    float* W1s = (float*)(smb + EN_W1);
    float* Ts  = (float*)(smb + EN_TS);
    float* Bs  = (float*)(smb + EN_BS);
    float* sB1 = (float*)(smb + EN_B1);
    float* sB2 = (float*)(smb + EN_B2);
    const int n0 = blockIdx.x * 128;
    const int tid = threadIdx.x;
    const int tx = tid & 15, ty = tid >> 4;
    const int row0 = ty * 8, col0 = tx * 8;

    for (int i = tid; i < FIN * 128; i += 256) {
        int k = i >> 7, nd = i & 127;
        Xs[k * NM + nd] = (n0 + nd < NN) ? x[(size_t)(n0 + nd) * FIN + k] : 0.0f;
        W1s[i] = w1[i];
    }
    if (tid < 128) { sB1[tid] = b1[tid]; sB2[tid] = b2[tid]; }
    __syncthreads();

    {
        float acc[8][8];
#pragma unroll
        for (int r = 0; r < 8; r++)
#pragma unroll
            for (int c = 0; c < 8; c++) acc[r][c] = 0.0f;
#pragma unroll
        for (int k = 0; k < FIN; k++) {
            float av[8], bv[8];
#pragma unroll
            for (int r = 0; r < 8; r++) av[r] = Xs[k * NM + row0 + r];
#pragma unroll
            for (int c = 0; c < 8; c++) bv[c] = W1s[k * 128 + col0 + c];
#pragma unroll
            for (int r = 0; r < 8; r++)
#pragma unroll
                for (int c = 0; c < 8; c++) acc[r][c] += av[r] * bv[c];
        }
#pragma unroll
        for (int r = 0; r < 8; r++)
#pragma unroll
            for (int c = 0; c < 8; c++)
                Ts[(col0 + c) * NM + row0 + r] = silu_m(acc[r][c] + sB1[col0 + c]);
    }
    __syncthreads();

    {
        float acc[8][8];
#pragma unroll
        for (int r = 0; r < 8; r++)
#pragma unroll
            for (int c = 0; c < 8; c++) acc[r][c] = 0.0f;
        for (int t = 0; t < 4; t++) {
#pragma unroll
            for (int it = 0; it < 4; ++it) {
                int i = tid + it * 256;
                int rowk = i >> 5, c4 = i & 31;
                *(float4*)&Bs[rowk * NM + c4 * 4] =
                    *(const float4*)&w2[(size_t)(t * 32 + rowk) * H + c4 * 4];
            }
            __syncthreads();
#pragma unroll 4
            for (int kk = 0; kk < 32; ++kk) {
                float av[8], bv[8];
                int k = t * 32 + kk;
#pragma unroll
                for (int r = 0; r < 8; r++) av[r] = Ts[k * NM + row0 + r];
                float4 b0 = *(const float4*)&Bs[kk * NM + col0];
                float4 b1v = *(const float4*)&Bs[kk * NM + col0 + 4];
                bv[0] = b0.x; bv[1] = b0.y; bv[2] = b0.z; bv[3] = b0.w;
                bv[4] = b1v.x; bv[5] = b1v.y; bv[6] = b1v.z; bv[7] = b1v.w;
#pragma unroll
                for (int r = 0; r < 8; r++)
#pragma unroll
                    for (int c = 0; c < 8; c++) acc[r][c] += av[r] * bv[c];
            }
            __syncthreads();
        }
#pragma unroll
        for (int r = 0; r < 8; r++) {
            int node = n0 + row0 + r;
            if (node < NN) {
                float* hp = &g_h[(size_t)node * H + col0];
                *(float4*)hp = make_float4(acc[r][0] + sB2[col0 + 0], acc[r][1] + sB2[col0 + 1],
                                           acc[r][2] + sB2[col0 + 2], acc[r][3] + sB2[col0 + 3]);
                *(float4*)(hp + 4) = make_float4(acc[r][4] + sB2[col0 + 4], acc[r][5] + sB2[col0 + 5],
                                                 acc[r][6] + sB2[col0 + 6], acc[r][7] + sB2[col0 + 7]);
            }
        }
    }
}

// ---------------- CSR edge sum (standalone, high occupancy) ----------------
__global__ void __launch_bounds__(256)
k_edgesum(const float* __restrict__ W1, const float* __restrict__ b1) {
    const int node = blockIdx.x * 8 + (threadIdx.x >> 5);
    if (node >= NN) return;
    const int lid = threadIdx.x & 31;
    const int c = lid * 4;
    const float4 wa = *(const float4*)&W1[256 * H + c];
    const float4 wb = *(const float4*)&W1[257 * H + c];
    const float4 wc = *(const float4*)&W1[258 * H + c];
    const float4 bb = *(const float4*)&b1[c];
    const float4 pa = *(const float4*)&g_P[(size_t)node * 256 + c];
    const float bx = pa.x + bb.x, by = pa.y + bb.y;
    const float bz = pa.z + bb.z, bw = pa.w + bb.w;
    float4 acc = make_float4(0.f, 0.f, 0.f, 0.f);
    int e = g_off[node];
    const int end = g_off[node + 1];
    if (e < end) {
        int src = g_ssrc[e];
        float4 eav = g_sea[e];
        float4 pb = *(const float4*)&g_P[(size_t)src * 256 + 128 + c];
        while (e < end) {
            const int en = e + 1;
            int srcN = src; float4 eavN = eav; float4 pbN = pb;
            if (en < end) {
                srcN = g_ssrc[en];
                eavN = g_sea[en];
                pbN = *(const float4*)&g_P[(size_t)srcN * 256 + 128 + c];
            }
            float v0 = bx + pb.x + eav.x * wa.x + eav.y * wb.x + eav.z * wc.x;
            float v1 = by + pb.y + eav.x * wa.y + eav.y * wb.y + eav.z * wc.y;
            float v2 = bz + pb.z + eav.x * wa.z + eav.y * wb.z + eav.z * wc.z;
            float v3 = bw + pb.w + eav.x * wa.w + eav.y * wb.w + eav.z * wc.w;
            acc.x += silu_m(v0);
            acc.y += silu_m(v1);
            acc.z += silu_m(v2);
            acc.w += silu_m(v3);
            e = en; src = srcN; eav = eavN; pb = pbN;
        }
    }
    const float iv = g_invdeg[node];
    acc.x *= iv; acc.y *= iv; acc.z *= iv; acc.w *= iv;
    *(float4*)&g_zsum[(size_t)node * H + c] = acc;
}

// ---------------- HMMA nodemlp: agg GEMM + residual + projection ---------
#define NB_AH 0
#define NB_AL 17408
#define NB_BH 34816
#define NB_BL 69632
#define NB_B2 104448
#define NB_MK 104960
#define NB_SMEM 105216

// warp-tile mma: 32 rows x 32 cols, 3-term bf16
__device__ __forceinline__ void mma_tile(uint32_t aH, uint32_t aL,
                                         uint32_t bH, uint32_t bL,
                                         int mrow, int ncol, int lid,
                                         float d[2][4][4]) {
    const int a_r = lid & 15, a_c8 = (lid >> 4) * 8;
    const int b_g = lid >> 3;
    const int b_n = (b_g >> 1) * 8 + (lid & 7);
    const int b_c8 = (b_g & 1) * 8;
#pragma unroll 1
    for (int ks = 0; ks < 8; ks++) {
        const int k0 = ks * 16;
        uint32_t ah[2][4], al[2][4];
#pragma unroll
        for (int mt = 0; mt < 2; mt++) {
            uint32_t addr = aH + (uint32_t)(mrow + mt * 16 + a_r) * 272
                          + (uint32_t)(k0 + a_c8) * 2;
            ldsm4(ah[mt], addr);
            ldsm4(al[mt], addr + (aL - aH));
        }
#pragma unroll
        for (int bt = 0; bt < 2; bt++) {
            uint32_t bh[4], bl[4];
            uint32_t addr = bH + (uint32_t)(ncol + bt * 16 + b_n) * 272
                          + (uint32_t)(k0 + b_c8) * 2;
            ldsm4(bh, addr);
            ldsm4(bl, addr + (bL - bH));
            const int nt0 = bt * 2, nt1 = nt0 + 1;
#pragma unroll
            for (int mt = 0; mt < 2; mt++) {
                mma16816(d[mt][nt0], ah[mt], bh[0], bh[1]);
                mma16816(d[mt][nt1], ah[mt], bh[2], bh[3]);
                mma16816(d[mt][nt0], ah[mt], bl[0], bl[1]);
                mma16816(d[mt][nt1], ah[mt], bl[2], bl[3]);
                mma16816(d[mt][nt0], al[mt], bh[0], bh[1]);
                mma16816(d[mt][nt1], al[mt], bh[2], bh[3]);
            }
        }
    }
}

__global__ void __launch_bounds__(256, 2)
k_nodemlp(int layer, const float* __restrict__ b2, int mode) {
    extern __shared__ char smb[];
    const uint32_t sb = smem_u32(smb);
    float* sB2 = (float*)(smb + NB_B2);
    float* sMk = (float*)(smb + NB_MK);
    const int tid = threadIdx.x;
    const int lid = tid & 31;
    const int wid = tid >> 5;
    const int n0 = blockIdx.x * 64;
    const int mrow = (wid & 1) * 32;
    const int ncol = (wid >> 1) * 32;
    const int fr = lid >> 2, fc = (lid & 3) * 2;

    if (mode != MD_PROJ) {
        if (tid < 128) sB2[tid] = b2[tid];
        if (tid < 64) {
            int node = n0 + tid;
            sMk[tid] = (node < NN && g_cnt[node] > 0) ? 1.0f : 0.0f;
        }
        // convert zsum tile -> As hi/lo
#pragma unroll
        for (int it = 0; it < 8; ++it) {
            int i = tid + it * 256;
            int nd = i >> 5, seg = i & 31;
            int node = n0 + nd;
            float4 v = make_float4(0.f, 0.f, 0.f, 0.f);
            if (node < NN) v = *(const float4*)&g_zsum[(size_t)node * H + seg * 4];
            __nv_bfloat16 h0 = __float2bfloat16_rn(v.x), h1 = __float2bfloat16_rn(v.y);
            __nv_bfloat16 h2 = __float2bfloat16_rn(v.z), h3 = __float2bfloat16_rn(v.w);
            uint2 uh, ul;
            uh.x = pack_bf16x2(v.x, v.y);
            uh.y = pack_bf16x2(v.z, v.w);
            ul.x = pack_bf16x2(v.x - __bfloat162float(h0), v.y - __bfloat162float(h1));
            ul.y = pack_bf16x2(v.z - __bfloat162float(h2), v.w - __bfloat162float(h3));
            *(uint2*)(smb + NB_AH + nd * 272 + seg * 8) = uh;
            *(uint2*)(smb + NB_AL + nd * 272 + seg * 8) = ul;
        }
        // load W2 image
        {
            const uint4* srcH = (const uint4*)(g_W2h + (size_t)layer * H * ASTR);
            const uint4* srcL = (const uint4*)(g_W2l + (size_t)layer * H * ASTR);
            uint4* dstH = (uint4*)(smb + NB_BH);
            uint4* dstL = (uint4*)(smb + NB_BL);
            for (int i = tid; i < 2176; i += 256) { dstH[i] = srcH[i]; dstL[i] = srcL[i]; }
        }
        __syncthreads();

        float d[2][4][4];
#pragma unroll
        for (int mt = 0; mt < 2; mt++)
#pragma unroll
            for (int nt = 0; nt < 4; nt++)
#pragma unroll
                for (int q = 0; q < 4; q++) d[mt][nt][q] = 0.0f;
        mma_tile(sb + NB_AH, sb + NB_AL, sb + NB_BH, sb + NB_BL, mrow, ncol, lid, d);
        __syncthreads();

        // epilogue: h_new = h + D + b2*mask -> g_h (+ As hi/lo if BOTH)
#pragma unroll
        for (int mt = 0; mt < 2; mt++) {
#pragma unroll
            for (int nt = 0; nt < 4; nt++) {
                int c = ncol + nt * 8 + fc;
#pragma unroll
                for (int half8 = 0; half8 < 2; half8++) {
                    int r = mrow + mt * 16 + fr + half8 * 8;
                    int node = n0 + r;
                    float d0 = d[mt][nt][half8 * 2 + 0];
                    float d1 = d[mt][nt][half8 * 2 + 1];
                    float hn0 = 0.f, hn1 = 0.f;
                    if (node < NN) {
                        float mk = sMk[r];
                        float2 hv = *(const float2*)&g_h[(size_t)node * H + c];
                        hn0 = hv.x + d0 + sB2[c] * mk;
                        hn1 = hv.y + d1 + sB2[c + 1] * mk;
                        *(float2*)&g_h[(size_t)node * H + c] = make_float2(hn0, hn1);
                    }
                    if (mode == MD_BOTH) {
                        __nv_bfloat16 b0 = __float2bfloat16_rn(hn0);
                        __nv_bfloat16 b1v = __float2bfloat16_rn(hn1);
                        *(uint32_t*)(smb + NB_AH + r * 272 + c * 2) = pack_bf16x2(hn0, hn1);
                        *(uint32_t*)(smb + NB_AL + r * 272 + c * 2) =
                            pack_bf16x2(hn0 - __bfloat162float(b0), hn1 - __bfloat162float(b1v));
                    }
                }
            }
        }
        if (mode == MD_AGG) return;
    } else {
        // PROJ: convert g_h tile -> As hi/lo
#pragma unroll
        for (int it = 0; it < 8; ++it) {
            int i = tid + it * 256;
            int nd = i >> 5, seg = i & 31;
            int node = n0 + nd;
            float4 v = make_float4(0.f, 0.f, 0.f, 0.f);
            if (node < NN) v = *(const float4*)&g_h[(size_t)node * H + seg * 4];
            __nv_bfloat16 h0 = __float2bfloat16_rn(v.x), h1 = __float2bfloat16_rn(v.y);
            __nv_bfloat16 h2 = __float2bfloat16_rn(v.z), h3 = __float2bfloat16_rn(v.w);
            uint2 uh, ul;
            uh.x = pack_bf16x2(v.x, v.y);
            uh.y = pack_bf16x2(v.z, v.w);
            ul.x = pack_bf16x2(v.x - __bfloat162float(h0), v.y - __bfloat162float(h1));
            ul.y = pack_bf16x2(v.z - __bfloat162float(h2), v.w - __bfloat162float(h3));
            *(uint2*)(smb + NB_AH + nd * 272 + seg * 8) = uh;
            *(uint2*)(smb + NB_AL + nd * 272 + seg * 8) = ul;
        }
    }

    // phase B: P = h_new @ [W1a | W1b] of layer lw (2 N-halves of 128)
    const int lw = (mode == MD_PROJ) ? 0 : layer + 1;
    for (int half = 0; half < 2; half++) {
        {
            const uint4* srcH = (const uint4*)(g_W1h + (size_t)(lw * 256 + half * 128) * ASTR);
            const uint4* srcL = (const uint4*)(g_W1l + (size_t)(lw * 256 + half * 128) * ASTR);
            uint4* dstH = (uint4*)(smb + NB_BH);
            uint4* dstL = (uint4*)(smb + NB_BL);
            for (int i = tid; i < 2176; i += 256) { dstH[i] = srcH[i]; dstL[i] = srcL[i]; }
        }
        __syncthreads();

        float d[2][4][4];
#pragma unroll
        for (int mt = 0; mt < 2; mt++)
#pragma unroll
            for (int nt = 0; nt < 4; nt++)
#pragma unroll
                for (int q = 0; q < 4; q++) d[mt][nt][q] = 0.0f;
        mma_tile(sb + NB_AH, sb + NB_AL, sb + NB_BH, sb + NB_BL, mrow, ncol, lid, d);

#pragma unroll
        for (int mt = 0; mt < 2; mt++) {
#pragma unroll
            for (int nt = 0; nt < 4; nt++) {
                int c = ncol + nt * 8 + fc;
#pragma unroll
                for (int half8 = 0; half8 < 2; half8++) {
                    int r = mrow + mt * 16 + fr + half8 * 8;
                    int node = n0 + r;
                    if (node < NN) {
                        *(float2*)&g_P[(size_t)node * 256 + half * 128 + c] =
                            make_float2(d[mt][nt][half8 * 2 + 0], d[mt][nt][half8 * 2 + 1]);
                    }
                }
            }
        }
        __syncthreads();
    }
}

// ---------------- tiled decoder ----------------
#define DE_HS 0
#define DE_BS (DE_HS + 128 * NM * 4)
#define DE_W3 (DE_BS + 32 * NM * 4)
#define DE_B1 (DE_W3 + 64 * FOUT * 4)
#define DE_B2 (DE_B1 + 512)
#define DE_B3 (DE_B2 + 256)
#define DE_SMEM (DE_B3 + 64)

__global__ void __launch_bounds__(256, 2)
k_decoder2(const float* __restrict__ w1, const float* __restrict__ b1,
           const float* __restrict__ w2, const float* __restrict__ b2,
           const float* __restrict__ w3, const float* __restrict__ b3,
           float* __restrict__ out) {
    extern __shared__ char smb[];
    float* Hs  = (float*)(smb + DE_HS);
    float* Bs  = (float*)(smb + DE_BS);
    float* w3s = (float*)(smb + DE_W3);
    float* sb1 = (float*)(smb + DE_B1);
    float* sb2 = (float*)(smb + DE_B2);
    float* sb3 = (float*)(smb + DE_B3);
    const int n0 = blockIdx.x * 128;
    const int tid = threadIdx.x;
    const int tx = tid & 15, ty = tid >> 4;
    const int row0 = ty * 8, col0 = tx * 8;

#pragma unroll
    for (int it = 0; it < 16; ++it) {
        int i = tid + it * 256;
        int nd = i >> 5, seg = i & 31;
        int node = n0 + nd;
        float4 v = make_float4(0.f, 0.f, 0.f, 0.f);
        if (node < NN) v = *(const float4*)&g_h[(size_t)node * H + seg * 4];
        Hs[(seg * 4 + 0) * NM + nd] = v.x;
        Hs[(seg * 4 + 1) * NM + nd] = v.y;
        Hs[(seg * 4 + 2) * NM + nd] = v.z;
        Hs[(seg * 4 + 3) * NM + nd] = v.w;
    }
    for (int i = tid; i < 64 * FOUT; i += 256) w3s[i] = w3[i];
    if (tid < 128) sb1[tid] = b1[tid];
    if (tid < 64) sb2[tid] = b2[tid];
    if (tid < FOUT) sb3[tid] = b3[tid];
    __syncthreads();

    float acc[8][8];
#pragma unroll
    for (int r = 0; r < 8; r++)
#pragma unroll
        for (int c = 0; c < 8; c++) acc[r][c] = 0.0f;
    for (int t = 0; t < 4; t++) {
#pragma unroll
        for (int it = 0; it < 4; ++it) {
            int i = tid + it * 256;
            int rowk = i >> 5, c4 = i & 31;
            *(float4*)&Bs[rowk * NM + c4 * 4] =
                *(const float4*)&w1[(size_t)(t * 32 + rowk) * H + c4 * 4];
        }
        __syncthreads();
#pragma unroll 4
        for (int kk = 0; kk < 32; ++kk) {
            int k = t * 32 + kk;
            float av[8], bv[8];
#pragma unroll
            for (int r = 0; r < 8; r++) av[r] = Hs[k * NM + row0 + r];
            float4 b0 = *(const float4*)&Bs[kk * NM + col0];
            float4 b1v = *(const float4*)&Bs[kk * NM + col0 + 4];
            bv[0] = b0.x; bv[1] = b0.y; bv[2] = b0.z; bv[3] = b0.w;
            bv[4] = b1v.x; bv[5] = b1v.y; bv[6] = b1v.z; bv[7] = b1v.w;
#pragma unroll
            for (int r = 0; r < 8; r++)
#pragma unroll
                for (int c = 0; c < 8; c++) acc[r][c] += av[r] * bv[c];
        }
        __syncthreads();
    }
#pragma unroll
    for (int r = 0; r < 8; r++)
#pragma unroll
        for (int c = 0; c < 8; c++)
            Hs[(col0 + c) * NM + row0 + r] = silu_m(acc[r][c] + sb1[col0 + c]);
    __syncthreads();

    const int col0b = tx * 4;
    float acc2[8][4];
#pragma unroll
    for (int r = 0; r < 8; r++)
#pragma unroll
        for (int c = 0; c < 4; c++) acc2[r][c] = 0.0f;
    for (int t = 0; t < 4; t++) {
#pragma unroll
        for (int it = 0; it < 2; ++it) {
            int i = tid + it * 256;
            int rowk = i >> 4, c4 = i & 15;
            *(float4*)&Bs[rowk * NM + c4 * 4] =
                *(const float4*)&w2[(size_t)(t * 32 + rowk) * 64 + c4 * 4];
        }
        __syncthreads();
#pragma unroll 4
        for (int kk = 0; kk < 32; ++kk) {
            int k = t * 32 + kk;
            float av[8];
#pragma unroll
            for (int r = 0; r < 8; r++) av[r] = Hs[k * NM + row0 + r];
            float4 b0 = *(const float4*)&Bs[kk * NM + col0b];
            float bv[4] = {b0.x, b0.y, b0.z, b0.w};
#pragma unroll
            for (int r = 0; r < 8; r++)
#pragma unroll
                for (int c = 0; c < 4; c++) acc2[r][c] += av[r] * bv[c];
        }
        __syncthreads();
    }
#pragma unroll
    for (int r = 0; r < 8; r++)
#pragma unroll
        for (int c = 0; c < 4; c++)
            Hs[(col0b + c) * NM + row0 + r] = silu_m(acc2[r][c] + sb2[col0b + c]);
    __syncthreads();

    {
        const int nd = tid >> 1;
        const int half = tid & 1;
        const int cbase = half * 5;
        const int ncols = half ? 4 : 5;
        float a3[5];
#pragma unroll
        for (int j = 0; j < 5; j++) a3[j] = 0.0f;
        for (int k = 0; k < 64; k++) {
            float tv = Hs[k * NM + nd];
#pragma unroll
            for (int j = 0; j < 5; j++)
                if (j < ncols) a3[j] += tv * w3s[k * FOUT + cbase + j];
        }
        int node = n0 + nd;
        if (node < NN) {
            for (int j = 0; j < ncols; j++)
                out[(size_t)node * FOUT + cbase + j] = a3[j] + sb3[cbase + j];
        }
    }
}

// ---------------- launch ----------------
extern "C" void kernel_launch(void* const* d_in, const int* in_sizes, int n_in,
                              void* d_out, int out_size) {
    const float* x      = (const float*)d_in[0];
    const void*  ei     = d_in[1];
    const float* ea     = (const float*)d_in[2];
    const float* enc_w1 = (const float*)d_in[3];
    const float* enc_b1 = (const float*)d_in[4];
    const float* enc_w2 = (const float*)d_in[5];
    const float* enc_b2 = (const float*)d_in[6];
    const float* conv_w1 = (const float*)d_in[7];
    const float* conv_b1 = (const float*)d_in[8];
    const float* conv_w2 = (const float*)d_in[9];
    const float* conv_b2 = (const float*)d_in[10];
    const float* dec_w1 = (const float*)d_in[11];
    const float* dec_b1 = (const float*)d_in[12];
    const float* dec_w2 = (const float*)d_in[13];
    const float* dec_b2 = (const float*)d_in[14];
    const float* dec_w3 = (const float*)d_in[15];
    const float* dec_b3 = (const float*)d_in[16];

    cudaFuncSetAttribute(k_encoder2, cudaFuncAttributeMaxDynamicSharedMemorySize, EN_SMEM);
    cudaFuncSetAttribute(k_nodemlp, cudaFuncAttributeMaxDynamicSharedMemorySize, NB_SMEM);
    cudaFuncSetAttribute(k_decoder2, cudaFuncAttributeMaxDynamicSharedMemorySize, DE_SMEM);

    k_pre0<<<(NN + 255) / 256, 256>>>((const int*)ei);
    k_convert<<<(EE + 255) / 256, 256>>>(ei);
    k_scan<<<1, 1024>>>();
    k_scatter<<<(EE + 255) / 256, 256>>>(ea);
    k_prepw<<<(W2_TOT + W1_TOT + 255) / 256, 256>>>(conv_w2, conv_w1);

    const int nTiles = (NN + 127) / 128;   // 157
    const int nT64   = (NN + 63) / 64;     // 313
    k_encoder2<<<nTiles, 256, EN_SMEM>>>(x, enc_w1, enc_b1, enc_w2, enc_b2);
    k_nodemlp<<<nT64, 256, NB_SMEM>>>(0, conv_b2, MD_PROJ);

    for (int l = 0; l < NLAYERS; l++) {
        k_edgesum<<<(NN + 7) / 8, 256>>>(conv_w1 + (size_t)l * 259 * H,
                                         conv_b1 + (size_t)l * H);
        k_nodemlp<<<nT64, 256, NB_SMEM>>>(l, conv_b2 + (size_t)l * H,
                                          (l + 1 < NLAYERS) ? MD_BOTH : MD_AGG);
    }

    k_decoder2<<<nTiles, 256, DE_SMEM>>>(dec_w1, dec_b1, dec_w2, dec_b2,
                                         dec_w3, dec_b3, (float*)d_out);
}